// round 15
// baseline (speedup 1.0000x reference)
#include <cuda_runtime.h>
#include <math.h>

#define N_SAMPLES 131072
#define N_EVENTS  128
#define N_ATOMS   32
#define ATOM_SIZE 512
#define LATENT    16
#define TIME_DIM  17
#define LAYERS    7

// ---------------- device-global scratch (no allocation allowed) ----------------
__device__ float g_xf[N_EVENTS * LATENT];            // final latent per event
__device__ int   g_pos[N_EVENTS];                    // dirac shift per event
__device__ float g_wave[N_EVENTS * ATOM_SIZE];       // pre-scaled waveforms

// 16-term dot product, serial FMA chain in ascending index order.
// EXACTLY the same association order as all prior passing kernels so the
// argmax bit decisions are bit-identical.
__device__ __forceinline__ float dot16(float4 w0, float4 w1, float4 w2, float4 w3,
                                       float4 x0, float4 x1, float4 x2, float4 x3,
                                       float init)
{
    float v = init;
    v = fmaf(x0.x, w0.x, v); v = fmaf(x0.y, w0.y, v);
    v = fmaf(x0.z, w0.z, v); v = fmaf(x0.w, w0.w, v);
    v = fmaf(x1.x, w1.x, v); v = fmaf(x1.y, w1.y, v);
    v = fmaf(x1.z, w1.z, v); v = fmaf(x1.w, w1.w, v);
    v = fmaf(x2.x, w2.x, v); v = fmaf(x2.y, w2.y, v);
    v = fmaf(x2.z, w2.z, v); v = fmaf(x2.w, w2.w, v);
    v = fmaf(x3.x, w3.x, v); v = fmaf(x3.y, w3.y, v);
    v = fmaf(x3.z, w3.z, v); v = fmaf(x3.w, w3.w, v);
    return v;
}

// sizes
#define WT_ELEMS (LAYERS * 68 * LATENT)   // 7616
#define WS_ELEMS (LAYERS * 32 * LATENT)   // 3584
#define BS_ELEMS (LAYERS * 32)            // 224
#define X_ELEMS  (N_EVENTS * LATENT)      // 2048
#define T_ELEMS  (N_EVENTS * 34)          // 4352

// smem weight cache: 7 layers x 100 rows, each padded to 20 floats (5 float4)
// stride 20 -> 8 consecutive lanes hit 8 distinct 16B bank groups: conflict-free
#define W_ROWS       (LAYERS * 100)           // 700
#define W_ROW_F4     5                        // 20 floats per row slot
#define W_SMEM_F     (W_ROWS * 20)            // 14000 floats
#define TREE_SMEM_FLOATS (W_SMEM_F + BS_ELEMS + 2 * X_ELEMS + 2 * T_ELEMS)  // 27024 = 108.1 KB

// ---------------- K1: binary tree — all weights staged in smem -----------------
// 1024 threads = 8 event-groups x 128 row-lanes.
//   r = tid & 127 : output row (r<68 time row; 68<=r<100 latent row; else idle)
//   g = tid >> 7  : event group; thread sweeps events e = g, g+8, ...
// All weights are copied GMEM->SMEM once (MLP-saturated burst), removing the
// per-layer LDG stall from the 7-layer serial dependency chain.
__global__ __launch_bounds__(1024, 1)
void tree_kernel(const float* __restrict__ base_latent,
                 const float* __restrict__ Wt,   // (7, 68, 16)
                 const float* __restrict__ Ws,   // (7, 32, 16)
                 const float* __restrict__ bs)   // (7, 32)
{
    extern __shared__ float sm[];
    float4* smw = (float4*)sm;                   // padded weight rows
    float*  smb = sm + W_SMEM_F;                 // 224 biases
    float*  sx  = smb + BS_ELEMS;                // 2 * 2048  ping-pong latent
    float*  st  = sx + 2 * X_ELEMS;              // 2 * 4352  ping-pong times

    const int tid = threadIdx.x;                 // 1024 threads

    // ---- one-shot weight staging (coalesced LDG.128, high MLP) ----
    {
        const float4* wt4 = (const float4*)Wt;   // 1904 float4
        for (int k = tid; k < WT_ELEMS / 4; k += 1024) {
            const int q = k >> 2, m = k & 3;     // source row, quarter
            const int i = q / 68, r = q - i * 68;
            smw[(i * 100 + r) * W_ROW_F4 + m] = wt4[k];
        }
        const float4* ws4 = (const float4*)Ws;   // 896 float4
        for (int k = tid; k < WS_ELEMS / 4; k += 1024) {
            const int q = k >> 2, m = k & 3;
            const int i = q / 32, j = q - i * 32;
            smw[(i * 100 + 68 + j) * W_ROW_F4 + m] = ws4[k];
        }
        if (tid < BS_ELEMS) smb[tid] = bs[tid];
    }
    if (tid < LATENT)       sx[tid] = base_latent[tid];
    if (tid < TIME_DIM * 2) st[tid] = 0.0f;
    __syncthreads();

    const int r = tid & 127;                     // row lane
    const int g = tid >> 7;                      // event group (0..7)

    const bool is_time = (r < 68);
    const bool is_lat  = (r >= 68) && (r < 100);
    const int  c  = r / 34;                      // time: child index
    const int  rr = r - c * 34;                  // time: (t*2 + s)
    const int  jl = r - 68;                      // latent row
    const int  ch = jl >> 4;                     // latent: child index
    const int  sl = jl & 15;                     // latent: slot

    for (int i = 0; i < LAYERS; i++) {
        // weight row for this layer from smem (conflict-free LDS.128)
        float4 w0 = {0,0,0,0}, w1 = {0,0,0,0}, w2 = {0,0,0,0}, w3 = {0,0,0,0};
        float  bias = 0.0f;
        if (is_time) {
            const float4* wp = smw + (i * 100 + r) * W_ROW_F4;
            w0 = wp[0]; w1 = wp[1]; w2 = wp[2]; w3 = wp[3];
        } else if (is_lat) {
            const float4* wp = smw + (i * 100 + 68 + jl) * W_ROW_F4;
            w0 = wp[0]; w1 = wp[1]; w2 = wp[2]; w3 = wp[3];
            bias = smb[i * 32 + jl];
        }

        const int n = 1 << i;
        const float* xA = sx + (i & 1) * X_ELEMS;
        float*       xB = sx + ((i & 1) ^ 1) * X_ELEMS;
        const float* tA = st + (i & 1) * T_ELEMS;
        float*       tB = st + ((i & 1) ^ 1) * T_ELEMS;

        if (is_time) {
            for (int e = g; e < n; e += 8) {
                const float4* xp = (const float4*)(xA + e * LATENT);  // broadcast
                const float4 x0 = xp[0], x1 = xp[1], x2 = xp[2], x3 = xp[3];
                const float v = dot16(w0, w1, w2, w3, x0, x1, x2, x3, 0.0f);
                tB[(2 * e + c) * 34 + rr] = tA[e * 34 + rr] + v;
            }
        } else if (is_lat) {
            for (int e = g; e < n; e += 8) {
                const float4* xp = (const float4*)(xA + e * LATENT);  // broadcast
                const float4 x0 = xp[0], x1 = xp[1], x2 = xp[2], x3 = xp[3];
                const float v = dot16(w0, w1, w2, w3, x0, x1, x2, x3, bias);
                xB[(2 * e + ch) * LATENT + sl] = v;
            }
        }
        __syncthreads();
    }

    // LAYERS = 7 (odd) -> final buffers in parity 1
    const float* xF = sx + X_ELEMS;
    const float* tF = st + T_ELEMS;

    for (int k = tid; k < X_ELEMS; k += 1024) g_xf[k] = xF[k];

    // argmax per event: strict >, MSB first (bit-identical to prior kernels)
    if (tid < N_EVENTS) {
        const int e = tid;
        int p = 0;
        #pragma unroll
        for (int t = 0; t < TIME_DIM; t++) {
            const int bit = tF[e * 34 + t * 2 + 1] > tF[e * 34 + t * 2 + 0];
            p |= bit << (TIME_DIM - 1 - t);
        }
        g_pos[e] = p;
    }
}

// ---------------- K2: per-event waveform (coeffs, window, norm, amp) -----------
// One block per event — identical numerics to the 33.3 us passing run.
__global__ void wave_kernel(const float* __restrict__ atoms,   // (32, 512)
                            const float* __restrict__ Wa,      // (32, 16)
                            const float* __restrict__ ba,      // (32,)
                            const float* __restrict__ Wamp,    // (1, 16)
                            const float* __restrict__ bamp)    // (1,)
{
    __shared__ float cs[N_ATOMS];
    __shared__ float s_amp;
    __shared__ float s_red[4];

    const int e   = blockIdx.x;
    const int tid = threadIdx.x;          // 128 threads
    const float* xe = g_xf + e * LATENT;

    if (tid < N_ATOMS) {
        float v = ba[tid];
        #pragma unroll
        for (int d = 0; d < LATENT; d++) v += xe[d] * Wa[tid * LATENT + d];
        cs[tid] = v;
    }
    if (tid == N_ATOMS) {
        float v = bamp[0];
        #pragma unroll
        for (int d = 0; d < LATENT; d++) v += xe[d] * Wamp[d];
        s_amp = v;
    }
    __syncthreads();

    float w[4];
    float sq = 0.0f;
    #pragma unroll
    for (int q = 0; q < 4; q++) {
        const int j = tid + q * 128;
        float v = 0.0f;
        #pragma unroll
        for (int k = 0; k < N_ATOMS; k++) v += cs[k] * atoms[k * ATOM_SIZE + j];
        // Hamming window: 0.54 - 0.46*cos(2*pi*j/512)
        const float win = 0.54f - 0.46f * cospif((float)j * (1.0f / 256.0f));
        v *= win;
        w[q] = v;
        sq += v * v;
    }

    // block reduce sum of squares (4 warps)
    #pragma unroll
    for (int o = 16; o > 0; o >>= 1) sq += __shfl_xor_sync(0xffffffffu, sq, o);
    if ((tid & 31) == 0) s_red[tid >> 5] = sq;
    __syncthreads();
    const float tot   = s_red[0] + s_red[1] + s_red[2] + s_red[3];
    const float scale = s_amp / (sqrtf(tot) + 1e-8f);

    #pragma unroll
    for (int q = 0; q < 4; q++)
        g_wave[e * ATOM_SIZE + tid + q * 128] = w[q] * scale;
}

// ---------------- K3: gather with ballot-built overlap list --------------------
// 256 blocks x 512 threads; block b owns samples [b*512, b*512+512).
// Threads 0..127 test event overlap once; set bits are walked in ascending
// event order -> accumulation order is BIT-IDENTICAL to the brute-force scan.
__global__ __launch_bounds__(512)
void gather_kernel(float* __restrict__ out)
{
    __shared__ int      ps[N_EVENTS];
    __shared__ unsigned ovm[4];

    const int tid = threadIdx.x;                 // 512 threads
    const int t0  = blockIdx.x * ATOM_SIZE;
    const int t   = t0 + tid;

    if (tid < N_EVENTS) ps[tid] = g_pos[tid];
    __syncthreads();

    if (tid < N_EVENTS) {                        // warps 0..3, full warps
        const int p = ps[tid];
        const bool f = (p < t0 + ATOM_SIZE) && (p + ATOM_SIZE > t0);
        const unsigned m = __ballot_sync(0xffffffffu, f);
        if ((tid & 31) == 0) ovm[tid >> 5] = m;
    }
    __syncthreads();

    float acc = 0.0f;
    #pragma unroll
    for (int w = 0; w < 4; w++) {
        unsigned m = ovm[w];
        while (m) {
            const int l = __ffs(m) - 1;
            m &= m - 1;
            const int e = w * 32 + l;            // ascending e within word, words ascending
            const unsigned off = (unsigned)(t - ps[e]);
            if (off < (unsigned)ATOM_SIZE) acc += g_wave[e * ATOM_SIZE + off];
        }
    }
    out[t] = acc;
}

// ---------------- launch -------------------------------------------------------
extern "C" void kernel_launch(void* const* d_in, const int* in_sizes, int n_in,
                              void* d_out, int out_size)
{
    // Robust input mapping by element count (all sizes unique except the two 16s,
    // where dict order gives base_latent before to_amp_W).
    const float *base_latent = nullptr, *Wt = nullptr, *Ws = nullptr, *bs = nullptr;
    const float *atoms = nullptr, *Wa = nullptr, *ba = nullptr, *Wamp = nullptr, *bamp = nullptr;
    for (int i = 0; i < n_in; i++) {
        const int s = in_sizes[i];
        const float* p = (const float*)d_in[i];
        switch (s) {
            case WT_ELEMS:              Wt = p;    break;   // 7616
            case WS_ELEMS:              Ws = p;    break;   // 3584
            case BS_ELEMS:              bs = p;    break;   // 224
            case N_ATOMS * ATOM_SIZE:   atoms = p; break;   // 16384
            case N_ATOMS * LATENT:      Wa = p;    break;   // 512
            case N_ATOMS:               ba = p;    break;   // 32
            case 1:                     bamp = p;  break;   // 1
            case LATENT:                                    // 16, twice
                if (!base_latent) base_latent = p; else Wamp = p;
                break;
            default: break;
        }
    }

    float* out = (float*)d_out;

    const int tree_smem = TREE_SMEM_FLOATS * (int)sizeof(float);   // ~108.1 KB
    cudaFuncSetAttribute(tree_kernel, cudaFuncAttributeMaxDynamicSharedMemorySize, tree_smem);

    tree_kernel<<<1, 1024, tree_smem>>>(base_latent, Wt, Ws, bs);
    wave_kernel<<<N_EVENTS, 128>>>(atoms, Wa, ba, Wamp, bamp);
    gather_kernel<<<N_SAMPLES / ATOM_SIZE, 512>>>(out);
    (void)out_size;
}

// round 16
// speedup vs baseline: 1.6342x; 1.6342x over previous
#include <cuda_runtime.h>
#include <math.h>

#define N_SAMPLES 131072
#define N_EVENTS  128
#define N_ATOMS   32
#define ATOM_SIZE 512
#define LATENT    16
#define TIME_DIM  17
#define LAYERS    7

// ---------------- device-global scratch (no allocation allowed) ----------------
__device__ int   g_pos[N_EVENTS];                    // dirac shift per event
__device__ float g_wave[N_EVENTS * ATOM_SIZE];       // pre-scaled waveforms

// 16-term dot product, serial FMA chain in ascending index order.
// EXACTLY the same association order as all prior passing kernels so the
// argmax bit decisions are bit-identical.
__device__ __forceinline__ float dot16(float4 w0, float4 w1, float4 w2, float4 w3,
                                       float4 x0, float4 x1, float4 x2, float4 x3,
                                       float init)
{
    float v = init;
    v = fmaf(x0.x, w0.x, v); v = fmaf(x0.y, w0.y, v);
    v = fmaf(x0.z, w0.z, v); v = fmaf(x0.w, w0.w, v);
    v = fmaf(x1.x, w1.x, v); v = fmaf(x1.y, w1.y, v);
    v = fmaf(x1.z, w1.z, v); v = fmaf(x1.w, w1.w, v);
    v = fmaf(x2.x, w2.x, v); v = fmaf(x2.y, w2.y, v);
    v = fmaf(x2.z, w2.z, v); v = fmaf(x2.w, w2.w, v);
    v = fmaf(x3.x, w3.x, v); v = fmaf(x3.y, w3.y, v);
    v = fmaf(x3.z, w3.z, v); v = fmaf(x3.w, w3.w, v);
    return v;
}

// sizes
#define WT_ELEMS (LAYERS * 68 * LATENT)   // 7616
#define WS_ELEMS (LAYERS * 32 * LATENT)   // 3584
#define BS_ELEMS (LAYERS * 32)            // 224

// per-block path weight cache: 7 levels x 50 rows (34 time + 16 latent),
// rows padded to 20 floats -> conflict-free LDS.128 within 8-lane phases
#define PW_ROWS      50
#define PW_ROW_F     20
#define PW_LEVEL_F   (PW_ROWS * PW_ROW_F)     // 1000
#define PW_SMEM_F    (LAYERS * PW_LEVEL_F)    // 7000 floats = 28 KB

// ---------------- K1: per-event path + position + waveform ---------------------
// 128 blocks x 128 threads. Block e computes ONLY event e's root-to-leaf path:
//   level i: parent latent -> child-half c_i = (e >> (6-i)) & 1
//     threads 0..33  : time rows   (t_acc[rr] += dot(x, Wt[i][c*34+rr]))
//     threads 34..49 : latent rows (x'[sl]   = dot(x, Ws[i][c*16+sl]) + b)
// All path weights prefetched into smem up-front (path known from blockIdx).
// Then the proven waveform phase runs on the in-smem final latent.
__global__ __launch_bounds__(128)
void path_wave_kernel(const float* __restrict__ base_latent,
                      const float* __restrict__ Wt,      // (7, 68, 16)
                      const float* __restrict__ Ws,      // (7, 32, 16)
                      const float* __restrict__ bs,      // (7, 32)
                      const float* __restrict__ atoms,   // (32, 512)
                      const float* __restrict__ Wa,      // (32, 16)
                      const float* __restrict__ ba,      // (32,)
                      const float* __restrict__ Wamp,    // (1, 16)
                      const float* __restrict__ bamp)    // (1,)
{
    __shared__ float smw[PW_SMEM_F];      // padded path weights
    __shared__ float smb[LAYERS * 16];    // path biases
    __shared__ float sx[2][LATENT];       // latent ping-pong
    __shared__ float stt[TIME_DIM * 2];   // accumulated times (34)
    __shared__ float cs[N_ATOMS];
    __shared__ float s_amp;
    __shared__ float s_red[4];

    const int e   = blockIdx.x;
    const int tid = threadIdx.x;          // 128 threads

    // ---- prefetch all 7 levels of path weights (coalesced, high MLP) ----
    for (int k = tid; k < LAYERS * PW_ROWS * LATENT; k += 128) {
        const int i   = k / (PW_ROWS * LATENT);
        const int rem = k - i * (PW_ROWS * LATENT);
        const int row = rem >> 4;          // 0..49
        const int el  = rem & 15;
        const int c   = (e >> (6 - i)) & 1;
        float v;
        if (row < 34) v = Wt[(i * 68 + c * 34 + row) * LATENT + el];
        else          v = Ws[(i * 32 + c * 16 + (row - 34)) * LATENT + el];
        smw[(i * PW_ROWS + row) * PW_ROW_F + el] = v;
    }
    if (tid < LAYERS * 16) {
        const int i  = tid >> 4;
        const int sl = tid & 15;
        const int c  = (e >> (6 - i)) & 1;
        smb[i * 16 + sl] = bs[i * 32 + c * 16 + sl];
    }
    if (tid < LATENT)       sx[0][tid] = base_latent[tid];
    if (tid < TIME_DIM * 2) stt[tid]   = 0.0f;
    __syncthreads();

    // ---- walk the path: 7 levels ----
    for (int i = 0; i < LAYERS; i++) {
        const float4* xp = (const float4*)sx[i & 1];          // broadcast LDS
        const float4 x0 = xp[0], x1 = xp[1], x2 = xp[2], x3 = xp[3];

        if (tid < 34) {
            const float4* wp = (const float4*)(smw + (i * PW_ROWS + tid) * PW_ROW_F);
            const float v = dot16(wp[0], wp[1], wp[2], wp[3], x0, x1, x2, x3, 0.0f);
            stt[tid] = stt[tid] + v;                          // same add order as tA + v
        } else if (tid < 50) {
            const int sl = tid - 34;
            const float4* wp = (const float4*)(smw + (i * PW_ROWS + tid) * PW_ROW_F);
            const float v = dot16(wp[0], wp[1], wp[2], wp[3], x0, x1, x2, x3,
                                  smb[i * 16 + sl]);
            sx[(i & 1) ^ 1][sl] = v;
        }
        __syncthreads();
    }

    // ---- position: strict >, MSB first (bit-identical comparisons) ----
    if (tid == 0) {
        int p = 0;
        #pragma unroll
        for (int t = 0; t < TIME_DIM; t++) {
            const int bit = stt[t * 2 + 1] > stt[t * 2 + 0];
            p |= bit << (TIME_DIM - 1 - t);
        }
        g_pos[e] = p;
    }

    // ---- waveform phase (proven numerics; LAYERS=7 odd -> final x in sx[1]) ----
    const float* xe = sx[1];

    if (tid < N_ATOMS) {
        float v = ba[tid];
        #pragma unroll
        for (int d = 0; d < LATENT; d++) v += xe[d] * Wa[tid * LATENT + d];
        cs[tid] = v;
    }
    if (tid == N_ATOMS) {
        float v = bamp[0];
        #pragma unroll
        for (int d = 0; d < LATENT; d++) v += xe[d] * Wamp[d];
        s_amp = v;
    }
    __syncthreads();

    float w[4];
    float sq = 0.0f;
    #pragma unroll
    for (int q = 0; q < 4; q++) {
        const int j = tid + q * 128;
        float v = 0.0f;
        #pragma unroll
        for (int k = 0; k < N_ATOMS; k++) v += cs[k] * atoms[k * ATOM_SIZE + j];
        // Hamming window: 0.54 - 0.46*cos(2*pi*j/512)
        const float win = 0.54f - 0.46f * cospif((float)j * (1.0f / 256.0f));
        v *= win;
        w[q] = v;
        sq += v * v;
    }

    // block reduce sum of squares (4 warps) — identical to proven wave kernel
    #pragma unroll
    for (int o = 16; o > 0; o >>= 1) sq += __shfl_xor_sync(0xffffffffu, sq, o);
    if ((tid & 31) == 0) s_red[tid >> 5] = sq;
    __syncthreads();
    const float tot   = s_red[0] + s_red[1] + s_red[2] + s_red[3];
    const float scale = s_amp / (sqrtf(tot) + 1e-8f);

    #pragma unroll
    for (int q = 0; q < 4; q++)
        g_wave[e * ATOM_SIZE + tid + q * 128] = w[q] * scale;
}

// ---------------- K2: deterministic gather of shifted waveforms ---------------
// Exact brute-force version from the 33.28 us passing run.
__global__ void gather_kernel(float* __restrict__ out)
{
    __shared__ int ps[N_EVENTS];
    const int tid = threadIdx.x;                 // 256 threads
    const int t0  = blockIdx.x * 256;
    const int t   = t0 + tid;

    if (tid < N_EVENTS) ps[tid] = g_pos[tid];
    __syncthreads();

    float acc = 0.0f;
    // fixed event order -> bit-deterministic float accumulation (no atomics)
    #pragma unroll 4
    for (int e = 0; e < N_EVENTS; e++) {
        const int p = ps[e];
        if (p < t0 + 256 && p + ATOM_SIZE > t0) {
            const unsigned off = (unsigned)(t - p);
            if (off < (unsigned)ATOM_SIZE) acc += g_wave[e * ATOM_SIZE + off];
        }
    }
    out[t] = acc;
}

// ---------------- launch -------------------------------------------------------
extern "C" void kernel_launch(void* const* d_in, const int* in_sizes, int n_in,
                              void* d_out, int out_size)
{
    // Robust input mapping by element count (all sizes unique except the two 16s,
    // where dict order gives base_latent before to_amp_W).
    const float *base_latent = nullptr, *Wt = nullptr, *Ws = nullptr, *bs = nullptr;
    const float *atoms = nullptr, *Wa = nullptr, *ba = nullptr, *Wamp = nullptr, *bamp = nullptr;
    for (int i = 0; i < n_in; i++) {
        const int s = in_sizes[i];
        const float* p = (const float*)d_in[i];
        switch (s) {
            case WT_ELEMS:              Wt = p;    break;   // 7616
            case WS_ELEMS:              Ws = p;    break;   // 3584
            case BS_ELEMS:              bs = p;    break;   // 224
            case N_ATOMS * ATOM_SIZE:   atoms = p; break;   // 16384
            case N_ATOMS * LATENT:      Wa = p;    break;   // 512
            case N_ATOMS:               ba = p;    break;   // 32
            case 1:                     bamp = p;  break;   // 1
            case LATENT:                                    // 16, twice
                if (!base_latent) base_latent = p; else Wamp = p;
                break;
            default: break;
        }
    }

    float* out = (float*)d_out;

    path_wave_kernel<<<N_EVENTS, 128>>>(base_latent, Wt, Ws, bs,
                                        atoms, Wa, ba, Wamp, bamp);
    gather_kernel<<<N_SAMPLES / 256, 256>>>(out);
    (void)out_size;
}